// round 4
// baseline (speedup 1.0000x reference)
#include <cuda_runtime.h>
#include <cuda_bf16.h>
#include <cstdint>

// ALiBi bias add: out[b,h,i,j] = scores[b,h,i,j] + (j - i) * slopes[h]
// Streaming, HBM-bound. 2x float4 per thread (MLP=2), shift/mask index math
// on the pow2 fast path (S=2048, H=16), 32-bit div fallback for odd shapes.

__device__ __forceinline__ void alibi_idx(unsigned e, unsigned S, unsigned H,
                                          float& d0, unsigned& h) {
    unsigned j, row, i, hb;
    if ((S & (S - 1u)) == 0u) {
        const unsigned sh = 31u - (unsigned)__clz((int)S);
        const unsigned m  = S - 1u;
        j   = e & m;
        row = e >> sh;
        i   = row & m;
        hb  = row >> sh;
    } else {
        j   = e % S;
        row = e / S;
        i   = row % S;
        hb  = row / S;
    }
    h  = ((H & (H - 1u)) == 0u) ? (hb & (H - 1u)) : (hb % H);
    d0 = (float)((int)j - (int)i);
}

__global__ void alibi_vec4x2_kernel(const float4* __restrict__ in,
                                    const float*  __restrict__ slopes,
                                    const int*    __restrict__ seq_len,
                                    float4*       __restrict__ out,
                                    unsigned n4, unsigned half, unsigned H) {
    const unsigned t = blockIdx.x * blockDim.x + threadIdx.x;
    if (t >= half) return;

    const unsigned S = (unsigned)__ldg(seq_len);  // uniform; L2-resident

    const unsigned i0 = t;
    const unsigned i1 = t + half;
    const bool has1  = (i1 < n4);
    const unsigned i1c = has1 ? i1 : (n4 - 1u);   // clamp: keep load unpredicated

    // Front-batch both loads unconditionally (MLP_p1 = 2)
    float4 v0 = in[i0];
    float4 v1 = in[i1c];

    float d0; unsigned h0;
    alibi_idx(i0 << 2, S, H, d0, h0);
    const float s0 = __ldg(&slopes[h0]);
    v0.x = fmaf(d0,        s0, v0.x);
    v0.y = fmaf(d0 + 1.0f, s0, v0.y);
    v0.z = fmaf(d0 + 2.0f, s0, v0.z);
    v0.w = fmaf(d0 + 3.0f, s0, v0.w);
    out[i0] = v0;

    if (has1) {
        float d1; unsigned h1;
        alibi_idx(i1 << 2, S, H, d1, h1);
        const float s1 = __ldg(&slopes[h1]);
        v1.x = fmaf(d1,        s1, v1.x);
        v1.y = fmaf(d1 + 1.0f, s1, v1.y);
        v1.z = fmaf(d1 + 2.0f, s1, v1.z);
        v1.w = fmaf(d1 + 3.0f, s1, v1.w);
        out[i1] = v1;
    }
}

// Scalar tail for n % 4 != 0 (not hit for S=2048, kept for shape variants).
__global__ void alibi_tail_kernel(const float* __restrict__ in,
                                  const float* __restrict__ slopes,
                                  const int*   __restrict__ seq_len,
                                  float*       __restrict__ out,
                                  unsigned base, unsigned n, unsigned H) {
    unsigned idx = base + blockIdx.x * blockDim.x + threadIdx.x;
    if (idx >= n) return;
    const unsigned S = (unsigned)__ldg(seq_len);
    unsigned j   = idx % S;
    unsigned row = idx / S;
    unsigned i   = row % S;
    unsigned h   = (row / S) % H;
    out[idx] = fmaf((float)((int)j - (int)i), slopes[h], in[idx]);
}

extern "C" void kernel_launch(void* const* d_in, const int* in_sizes, int n_in,
                              void* d_out, int out_size) {
    const float4* in     = (const float4*)d_in[0];
    const float*  slopes = (const float*)d_in[1];
    const int*    seq    = (const int*)d_in[2];
    float4*       out    = (float4*)d_out;

    const unsigned n    = (unsigned)in_sizes[0];
    const unsigned H    = (unsigned)in_sizes[1];
    const unsigned n4   = n >> 2;
    const unsigned half = (n4 + 1u) >> 1;

    if (half > 0) {
        const unsigned threads = 256;
        const unsigned blocks  = (half + threads - 1) / threads;
        alibi_vec4x2_kernel<<<blocks, threads>>>(in, slopes, seq, out, n4, half, H);
    }

    const unsigned tail = n & 3u;
    if (tail) {
        alibi_tail_kernel<<<1, 32>>>((const float*)d_in[0], slopes, seq,
                                     (float*)d_out, n4 << 2, n, H);
    }
}